// round 14
// baseline (speedup 1.0000x reference)
#include <cuda_runtime.h>
#include <cuda_bf16.h>
#include <cstdint>

// ---------------------------------------------------------------------------
// Fused edge-MLP, algebraic node/edge factorization + WARP-SPECIALIZED edge:
//   y1 = x1 @ W1[:128], y2 = x2 @ W1[128:]     (per NODE)   -- node_kernel
//   edge: h = relu(y1[src]+y2[dst]+b1)  -> H SMEM (producers, warps 0-7)
//         D2 = W2^T @ h (tcgen05)       -> drain+fold+store (consumers, 8-15)
//         out = relu(D2+b2).W3 + b3
// 3-term bf16 split everywhere = fp32-class accuracy.
// Edge TMEM: W2h 0-63 | W2l 64-127 | D0 128-255 | D1 256-383.
// Double-buffered H; mbarrier ring full/empty/mma/ddone; producers stream
// gathers continuously (LTS stays saturated), consumers hide underneath.
// ---------------------------------------------------------------------------

#if defined(__CUDA_ARCH__) && defined(__CUDA_ARCH_FEAT_SM103_ALL)
#define EDGE_USE_TC 1
#else
#define EDGE_USE_TC 0
#endif

#define NT      512
#define TILE_M  128
#define GRID    148
#define MAXN    100096

// idesc kind::f16: F32 accum, BF16 a/b, N=128, M=128
#define IDESC   0x8200490u

// node kernel SMEM
#define A_PH      0
#define A_PL      32768
#define A_TMEMPTR 65536
#define A_BAR     65544
#define A_TOTAL   65568

// edge kernel SMEM
#define B_HH(b)   ((b) * 65536)            // 32KB hi
#define B_HL(b)   ((b) * 65536 + 32768)    // 32KB lo
#define B_RED     131072                   // 4 x 128 fp32
#define B_TMEMPTR 133120
#define BAR_FULL  133128                   // 2 x 8B, count 8 (producers)
#define BAR_EMPTY 133144                   // 2 x 8B, count 8 (consumers)
#define BAR_MMA   133160                   // 2 x 8B, count 1 (commit)
#define BAR_DDONE 133176                   // 2 x 8B, count 8 (consumers)
#define B_TOTAL   133216

// Prepared weights (transposed+packed for TMEM A-operand):
// word(m, c) = bf16(W[2c, m]) | bf16(W[2c+1, m])<<16  (hi and lo splits)
__device__ __align__(16) uint32_t g_W1at_h[8192];   // W1[0:128]^T  [m=128][c=64]
__device__ __align__(16) uint32_t g_W1at_l[8192];
__device__ __align__(16) uint32_t g_W1bt_h[8192];   // W1[128:256]^T
__device__ __align__(16) uint32_t g_W1bt_l[8192];
__device__ __align__(16) uint32_t g_W2t_h[8192];    // W2^T
__device__ __align__(16) uint32_t g_W2t_l[8192];

// Per-node layer-1 partials (fp32), written by node_kernel.
__device__ __align__(16) float g_y1[(size_t)MAXN * 128];
__device__ __align__(16) float g_y2[(size_t)MAXN * 128];

__device__ __forceinline__ int sw128(int off) { return off ^ ((off >> 3) & 0x70); }

#if EDGE_USE_TC

__device__ __forceinline__ uint32_t smem_u32_of(const void* p) {
    uint32_t a;
    asm("{ .reg .u64 t; cvta.to.shared.u64 t, %1; cvt.u32.u64 %0, t; }"
        : "=r"(a) : "l"(p));
    return a;
}
__device__ __forceinline__ uint32_t elect_one() {
    uint32_t pred;
    asm volatile("{ .reg .pred p; elect.sync _|p, 0xFFFFFFFF; selp.b32 %0, 1, 0, p; }"
                 : "=r"(pred));
    return pred;
}
__device__ __forceinline__ uint64_t smem_desc(uint32_t addr) {
    // SW128, Blackwell version=1, SBO=64, LBO=1 (K-major)
    return 0x4000404000010000ULL | ((uint64_t)(addr >> 4) & 0x3FFF);
}
__device__ __forceinline__ void mma_f16_ts(uint32_t d_tmem, uint32_t a_tmem,
                                           uint64_t b_desc, uint32_t en) {
    asm volatile(
        "{\n\t.reg .pred p;\n\tsetp.ne.u32 p, %4, 0;\n\t"
        "tcgen05.mma.cta_group::1.kind::f16 [%0], [%1], %2, %3, {%5,%5,%5,%5}, p;\n\t}"
        :: "r"(d_tmem), "r"(a_tmem), "l"(b_desc), "r"(IDESC), "r"(en), "r"(0u)
        : "memory");
}

#define TCGEN05_ALLOC(sa, n) \
    asm volatile("tcgen05.alloc.cta_group::1.sync.aligned.shared::cta.b32 [%0], %1;" \
                 :: "r"((uint32_t)(sa)), "r"((uint32_t)(n)) : "memory")
#define TCGEN05_DEALLOC(t, n) \
    asm volatile("tcgen05.dealloc.cta_group::1.sync.aligned.b32 %0, %1;" \
                 :: "r"(t), "r"((uint32_t)(n)))
#define TCGEN05_COMMIT(mb) \
    asm volatile("tcgen05.commit.cta_group::1.mbarrier::arrive::one.shared::cluster.b64 [%0];" \
                 :: "r"((uint32_t)(mb)) : "memory")
#define TCGEN05_WAIT_LD()  asm volatile("tcgen05.wait::ld.sync.aligned;" ::: "memory")
#define TCGEN05_WAIT_ST()  asm volatile("tcgen05.wait::st.sync.aligned;" ::: "memory")
#define TCGEN05_FENCE_BEFORE() asm volatile("tcgen05.fence::before_thread_sync;" ::: "memory")
#define TCGEN05_FENCE_AFTER()  asm volatile("tcgen05.fence::after_thread_sync;" ::: "memory")
#define FENCE_ASYNC() asm volatile("fence.proxy.async.shared::cta;" ::: "memory")
#define MBARRIER_INIT(mb, c) \
    asm volatile("mbarrier.init.shared.b64 [%0], %1;" :: "r"((uint32_t)(mb)), "r"((uint32_t)(c)) : "memory")
#define MBARRIER_INVAL(mb) \
    asm volatile("mbarrier.inval.shared.b64 [%0];" :: "r"((uint32_t)(mb)) : "memory")
#define MBARRIER_ARRIVE(mb) \
    asm volatile("mbarrier.arrive.shared.b64 _, [%0];" :: "r"((uint32_t)(mb)) : "memory")
#define NAMED_BAR(id, n) \
    asm volatile("bar.sync %0, %1;" :: "r"(id), "r"(n) : "memory")

#define MBARRIER_WAIT_PARITY(mb, ph) do {                                          \
    uint32_t _m = (uint32_t)(mb), _p = (uint32_t)(ph), _done;                      \
    asm volatile("{\n\t.reg .pred p;\n\t"                                          \
        "mbarrier.try_wait.parity.acquire.cta.shared::cta.b64 p, [%1], %2;\n\t"    \
        "selp.b32 %0, 1, 0, p;\n\t}" : "=r"(_done) : "r"(_m), "r"(_p) : "memory"); \
    if (!_done) {                                                                  \
        asm volatile("{\n\t.reg .pred P1;\n\t"                                     \
        "WL_%=:\n\t"                                                               \
        "mbarrier.try_wait.parity.acquire.cta.shared::cta.b64 P1, [%0], %1, 0x989680;\n\t" \
        "@P1 bra.uni WD_%=;\n\t"                                                   \
        "bra.uni WL_%=;\n\t"                                                       \
        "WD_%=:\n\t}" :: "r"(_m), "r"(_p) : "memory");                             \
    }                                                                              \
} while (0)

#define LDTM_X32(r, a)                                                             \
    asm volatile("tcgen05.ld.sync.aligned.32x32b.x32.b32 "                         \
        "{%0,%1,%2,%3,%4,%5,%6,%7,%8,%9,%10,%11,%12,%13,%14,%15,"                  \
        "%16,%17,%18,%19,%20,%21,%22,%23,%24,%25,%26,%27,%28,%29,%30,%31}, [%32];" \
        : "=r"((r)[0]),"=r"((r)[1]),"=r"((r)[2]),"=r"((r)[3]),                     \
          "=r"((r)[4]),"=r"((r)[5]),"=r"((r)[6]),"=r"((r)[7]),                     \
          "=r"((r)[8]),"=r"((r)[9]),"=r"((r)[10]),"=r"((r)[11]),                   \
          "=r"((r)[12]),"=r"((r)[13]),"=r"((r)[14]),"=r"((r)[15]),                 \
          "=r"((r)[16]),"=r"((r)[17]),"=r"((r)[18]),"=r"((r)[19]),                 \
          "=r"((r)[20]),"=r"((r)[21]),"=r"((r)[22]),"=r"((r)[23]),                 \
          "=r"((r)[24]),"=r"((r)[25]),"=r"((r)[26]),"=r"((r)[27]),                 \
          "=r"((r)[28]),"=r"((r)[29]),"=r"((r)[30]),"=r"((r)[31])                  \
        : "r"(a))

#define STTM_X32(a, r)                                                             \
    asm volatile("tcgen05.st.sync.aligned.32x32b.x32.b32 [%0], "                   \
        "{%1,%2,%3,%4,%5,%6,%7,%8,%9,%10,%11,%12,%13,%14,%15,%16,"                 \
        "%17,%18,%19,%20,%21,%22,%23,%24,%25,%26,%27,%28,%29,%30,%31,%32};"        \
        :: "r"(a),                                                                 \
           "r"((r)[0]),"r"((r)[1]),"r"((r)[2]),"r"((r)[3]),                        \
           "r"((r)[4]),"r"((r)[5]),"r"((r)[6]),"r"((r)[7]),                        \
           "r"((r)[8]),"r"((r)[9]),"r"((r)[10]),"r"((r)[11]),                      \
           "r"((r)[12]),"r"((r)[13]),"r"((r)[14]),"r"((r)[15]),                    \
           "r"((r)[16]),"r"((r)[17]),"r"((r)[18]),"r"((r)[19]),                    \
           "r"((r)[20]),"r"((r)[21]),"r"((r)[22]),"r"((r)[23]),                    \
           "r"((r)[24]),"r"((r)[25]),"r"((r)[26]),"r"((r)[27]),                    \
           "r"((r)[28]),"r"((r)[29]),"r"((r)[30]),"r"((r)[31])                     \
        : "memory")

__device__ __forceinline__ uint32_t pack_bf2f(float a, float b) {
    __nv_bfloat162 t = __floats2bfloat162_rn(a, b);   // .x = low half
    return *reinterpret_cast<uint32_t*>(&t);
}

#endif  // EDGE_USE_TC

// ------------------------------ prep kernel -------------------------------
__global__ void prep_kernel(const float* __restrict__ W1,
                            const float* __restrict__ W2) {
    int i = blockIdx.x * blockDim.x + threadIdx.x;
    const float* src = nullptr;
    uint32_t *dh = nullptr, *dl = nullptr;
    int j = i, kofs = 0;
    if (i < 8192)       { src = W1; dh = g_W1at_h; dl = g_W1at_l; kofs = 0;   }
    else if (i < 16384) { src = W1; dh = g_W1bt_h; dl = g_W1bt_l; kofs = 128; j = i - 8192;  }
    else if (i < 24576) { src = W2; dh = g_W2t_h;  dl = g_W2t_l;  kofs = 0;   j = i - 16384; }
    else return;
    int m = j >> 6, c = j & 63;
    float a = src[(kofs + 2 * c) * 128 + m];
    float b = src[(kofs + 2 * c + 1) * 128 + m];
    __nv_bfloat16 ah = __float2bfloat16_rn(a), bh = __float2bfloat16_rn(b);
    float al = a - __bfloat162float(ah), bl = b - __bfloat162float(bh);
    __nv_bfloat162 hi; hi.x = ah; hi.y = bh;
    __nv_bfloat162 lo = __floats2bfloat162_rn(al, bl);
    dh[j] = *reinterpret_cast<uint32_t*>(&hi);
    dl[j] = *reinterpret_cast<uint32_t*>(&lo);
}

// --------------------------- node precompute kernel ------------------------
__global__ __launch_bounds__(NT, 1)
void node_kernel(const float* __restrict__ x1, const float* __restrict__ x2,
                 int N) {
#if EDGE_USE_TC
    extern __shared__ char smem[];
    const uint32_t sb = smem_u32_of(smem);
    const int tid  = threadIdx.x;
    const int lane = tid & 31;
    const int wid  = tid >> 5;
    const int sp   = wid & 3;
    const int cc   = wid >> 2;
    const uint32_t rowbits = (uint32_t)sp << 21;
    const int g    = sp * 32 + lane;

    if (wid == 0) TCGEN05_ALLOC(sb + A_TMEMPTR, 512);
    if (tid == 0) MBARRIER_INIT(sb + A_BAR, 1);
    __syncthreads();
    uint32_t tmem;
    asm volatile("ld.shared.b32 %0, [%1];" : "=r"(tmem) : "r"(sb + A_TMEMPTR));
    const uint32_t tD = tmem + 256;

    // upload W1a (cols 0-127) and W1b (cols 128-255)
    {
        uint32_t ww[32];
        if (wid < 4) {
#pragma unroll
            for (int q = 0; q < 2; ++q) {
#pragma unroll
                for (int i = 0; i < 32; ++i) ww[i] = g_W1at_h[g * 64 + 32 * q + i];
                STTM_X32(tmem + 32 * q + rowbits, ww);
            }
#pragma unroll
            for (int q = 0; q < 2; ++q) {
#pragma unroll
                for (int i = 0; i < 32; ++i) ww[i] = g_W1at_l[g * 64 + 32 * q + i];
                STTM_X32(tmem + 64 + 32 * q + rowbits, ww);
            }
            TCGEN05_WAIT_ST();
        } else if (wid < 8) {
#pragma unroll
            for (int q = 0; q < 2; ++q) {
#pragma unroll
                for (int i = 0; i < 32; ++i) ww[i] = g_W1bt_h[g * 64 + 32 * q + i];
                STTM_X32(tmem + 128 + 32 * q + rowbits, ww);
            }
#pragma unroll
            for (int q = 0; q < 2; ++q) {
#pragma unroll
                for (int i = 0; i < 32; ++i) ww[i] = g_W1bt_l[g * 64 + 32 * q + i];
                STTM_X32(tmem + 192 + 32 * q + rowbits, ww);
            }
            TCGEN05_WAIT_ST();
        }
    }
    TCGEN05_FENCE_BEFORE();
    __syncthreads();

    const int nt1 = (N + 127) / 128;
    const int total = 2 * nt1;
    const int coff = 8 * (lane & 15);
    const int csel = lane >> 4;
    int ph = 0;

    for (int tt = blockIdx.x; tt < total; tt += GRID) {
        const int mt = (tt >= nt1);
        const int tile = mt ? tt - nt1 : tt;
        const float* xb = mt ? x2 : x1;
        float* yb = mt ? g_y2 : g_y1;
        const uint32_t aT = tmem + (mt ? 128u : 0u);

#pragma unroll
        for (int i = 0; i < 8; ++i) {
            int r = wid * 8 + i;
            long long node = (long long)tile * 128 + r;
            float4 v = make_float4(0.f, 0.f, 0.f, 0.f);
            if (node < N)
                v = reinterpret_cast<const float4*>(xb + node * 128)[lane];
            __nv_bfloat162 h0 = __floats2bfloat162_rn(v.x, v.y);
            __nv_bfloat162 h1 = __floats2bfloat162_rn(v.z, v.w);
            uint2 hh = make_uint2(*reinterpret_cast<uint32_t*>(&h0),
                                  *reinterpret_cast<uint32_t*>(&h1));
            uint2 ll = make_uint2(pack_bf2f(v.x - __bfloat162float(h0.x),
                                            v.y - __bfloat162float(h0.y)),
                                  pack_bf2f(v.z - __bfloat162float(h1.x),
                                            v.w - __bfloat162float(h1.y)));
            int off = csel * 16384 + sw128(r * 128 + coff);
            *reinterpret_cast<uint2*>(smem + A_PH + off) = hh;
            *reinterpret_cast<uint2*>(smem + A_PL + off) = ll;
        }
        FENCE_ASYNC();
        __syncthreads();

        if (wid == 4 && elect_one()) {
            TCGEN05_FENCE_AFTER();
#pragma unroll
            for (int pass = 0; pass < 3; ++pass) {
                const uint32_t acol = (pass == 2) ? 64u : 0u;
                const uint32_t bbase = (pass == 1) ? A_PL : A_PH;
                for (int c = 0; c < 2; ++c) {
                    uint64_t bd = smem_desc(sb + bbase + c * 16384);
                    for (int k = 0; k < 4; ++k)
                        mma_f16_ts(tD, aT + acol + (c * 4 + k) * 8, bd + k * 2,
                                   (pass == 0 && c == 0 && k == 0) ? 0u : 1u);
                }
            }
            TCGEN05_COMMIT(sb + A_BAR);
        }
        MBARRIER_WAIT_PARITY(sb + A_BAR, ph); ph ^= 1;
        TCGEN05_FENCE_AFTER();

        uint32_t d[32];
        LDTM_X32(d, tD + 32 * cc);
        TCGEN05_WAIT_LD();
#pragma unroll
        for (int j = 0; j < 32; ++j) {
            long long node = (long long)tile * 128 + cc * 32 + j;
            if (node < N) yb[node * 128 + g] = __uint_as_float(d[j]);
        }
    }

    __syncthreads();
    if (tid == 0) MBARRIER_INVAL(sb + A_BAR);
    __syncthreads();
    if (wid == 0) TCGEN05_DEALLOC(tmem, 512);
#else
    (void)x1; (void)x2; (void)N;
#endif
}

// --------------------- edge kernel (warp-specialized) ----------------------
__global__ __launch_bounds__(NT, 1)
void edge_kernel(const int* __restrict__ ei,
                 const float* __restrict__ b1g,
                 const float* __restrict__ b2g,
                 const float* __restrict__ W3g,
                 const float* __restrict__ b3g,
                 float* __restrict__ out, int E) {
#if EDGE_USE_TC
    extern __shared__ char smem[];
    const uint32_t sb = smem_u32_of(smem);
    const int tid  = threadIdx.x;
    const int lane = tid & 31;
    const int wid  = tid >> 5;
    const int sp   = wid & 3;
    const uint32_t rowbits = (uint32_t)sp << 21;
    const int g    = sp * 32 + lane;
    const int ntiles = (E + TILE_M - 1) / TILE_M;

    if (wid == 0) TCGEN05_ALLOC(sb + B_TMEMPTR, 512);
    if (tid == 0) {
        MBARRIER_INIT(sb + BAR_FULL,      8); MBARRIER_INIT(sb + BAR_FULL + 8,  8);
        MBARRIER_INIT(sb + BAR_EMPTY,     8); MBARRIER_INIT(sb + BAR_EMPTY + 8, 8);
        MBARRIER_INIT(sb + BAR_MMA,       1); MBARRIER_INIT(sb + BAR_MMA + 8,   1);
        MBARRIER_INIT(sb + BAR_DDONE,     8); MBARRIER_INIT(sb + BAR_DDONE + 8, 8);
    }
    __syncthreads();
    uint32_t tmem;
    asm volatile("ld.shared.b32 %0, [%1];" : "=r"(tmem) : "r"(sb + B_TMEMPTR));

    // upload W2 (hi cols 0-63, lo cols 64-127) -- warps 0-3
    if (wid < 4) {
        uint32_t ww[32];
#pragma unroll
        for (int q = 0; q < 2; ++q) {
#pragma unroll
            for (int i = 0; i < 32; ++i) ww[i] = g_W2t_h[g * 64 + 32 * q + i];
            STTM_X32(tmem + 32 * q + rowbits, ww);
        }
#pragma unroll
        for (int q = 0; q < 2; ++q) {
#pragma unroll
            for (int i = 0; i < 32; ++i) ww[i] = g_W2t_l[g * 64 + 32 * q + i];
            STTM_X32(tmem + 64 + 32 * q + rowbits, ww);
        }
        TCGEN05_WAIT_ST();
    }
    TCGEN05_FENCE_BEFORE();
    __syncthreads();   // last __syncthreads before the specialized loops

    if (wid < 8) {
        // ===================== PRODUCERS (warps 0-7) =======================
        const float4 b1v4 = reinterpret_cast<const float4*>(b1g)[lane];
        const int coff  = 8 * (lane & 15);
        const int csel  = lane >> 4;
        const int mbase = wid * 16;

        int iter = 0;
        for (int t = blockIdx.x; t < ntiles; t += GRID, ++iter) {
            const int b = iter & 1, k = iter >> 1;
            if (iter >= 2)
                MBARRIER_WAIT_PARITY(sb + BAR_EMPTY + 8 * b, (k - 1) & 1);

            int eidx = t * TILE_M + mbase + (lane & 15);
            int nd = -1;
            if (eidx < E)
                nd = ei[(lane >= 16 ? (long long)E : 0ll) + eidx];

#pragma unroll
            for (int r = 0; r < 4; ++r) {
                float4 va[4], vb[4];
#pragma unroll
                for (int i = 0; i < 4; ++i) {
                    int s = __shfl_sync(0xffffffffu, nd, r * 4 + i);
                    int d = __shfl_sync(0xffffffffu, nd, 16 + r * 4 + i);
                    va[i] = (s >= 0)
                        ? reinterpret_cast<const float4*>(g_y1 + (long long)s * 128)[lane]
                        : make_float4(0.f, 0.f, 0.f, 0.f);
                    vb[i] = (d >= 0)
                        ? reinterpret_cast<const float4*>(g_y2 + (long long)d * 128)[lane]
                        : make_float4(0.f, 0.f, 0.f, 0.f);
                }
#pragma unroll
                for (int i = 0; i < 4; ++i) {
                    int m = mbase + r * 4 + i;
                    float v0 = fmaxf(va[i].x + vb[i].x + b1v4.x, 0.f);
                    float v1 = fmaxf(va[i].y + vb[i].y + b1v4.y, 0.f);
                    float v2 = fmaxf(va[i].z + vb[i].z + b1v4.z, 0.f);
                    float v3 = fmaxf(va[i].w + vb[i].w + b1v4.w, 0.f);
                    __nv_bfloat162 h0 = __floats2bfloat162_rn(v0, v1);
                    __nv_bfloat162 h1 = __floats2bfloat162_rn(v2, v3);
                    uint2 hh = make_uint2(*reinterpret_cast<uint32_t*>(&h0),
                                          *reinterpret_cast<uint32_t*>(&h1));
                    uint2 ll = make_uint2(pack_bf2f(v0 - __bfloat162float(h0.x),
                                                    v1 - __bfloat162float(h0.y)),
                                          pack_bf2f(v2 - __bfloat162float(h1.x),
                                                    v3 - __bfloat162float(h1.y)));
                    int off = csel * 16384 + sw128(m * 128 + coff);
                    *reinterpret_cast<uint2*>(smem + B_HH(b) + off) = hh;
                    *reinterpret_cast<uint2*>(smem + B_HL(b) + off) = ll;
                }
            }
            FENCE_ASYNC();
            __syncwarp();
            if (elect_one()) MBARRIER_ARRIVE(sb + BAR_FULL + 8 * b);
        }
    } else {
        // ===================== CONSUMERS (warps 8-15) ======================
        const int cw  = wid - 8;
        const int cc0 = (cw >> 2) * 2;     // chunks {0,1} or {2,3}
        const float b2v = b2g[g];
        const float w3v = W3g[g];
        const float b3v = b3g[0];
        float* red = (float*)(smem + B_RED);
        const int tt2 = tid - 256;         // 0..255 within consumer half

        int iter = 0;
        for (int t = blockIdx.x; t < ntiles; t += GRID, ++iter) {
            const int b = iter & 1, k = iter >> 1;
            const uint32_t tD = tmem + 128 + 128 * (uint32_t)b;

            MBARRIER_WAIT_PARITY(sb + BAR_FULL + 8 * b, k & 1);

            if (wid == 8 && elect_one()) {
                if (iter >= 2)
                    MBARRIER_WAIT_PARITY(sb + BAR_DDONE + 8 * b, (k - 1) & 1);
                TCGEN05_FENCE_AFTER();
#pragma unroll
                for (int pass = 0; pass < 3; ++pass) {
                    const uint32_t acol = (pass == 2) ? 64u : 0u;
                    const uint32_t bbase = (pass == 1) ? B_HL(b) : B_HH(b);
                    for (int c = 0; c < 2; ++c) {
                        uint64_t bd = smem_desc(sb + bbase + c * 16384);
                        for (int kk = 0; kk < 4; ++kk)
                            mma_f16_ts(tD, tmem + acol + (c * 4 + kk) * 8,
                                       bd + kk * 2,
                                       (pass == 0 && c == 0 && kk == 0) ? 0u : 1u);
                    }
                }
                TCGEN05_COMMIT(sb + BAR_MMA + 8 * b);
            }

            MBARRIER_WAIT_PARITY(sb + BAR_MMA + 8 * b, k & 1);
            TCGEN05_FENCE_AFTER();
            // MMA done => H[b] fully read: release to producers immediately.
            if (elect_one()) MBARRIER_ARRIVE(sb + BAR_EMPTY + 8 * b);

            // drain + fold (2 chunks of 32 cols per warp)
#pragma unroll
            for (int q = 0; q < 2; ++q) {
                const int cc = cc0 + q;
                uint32_t d[32];
                LDTM_X32(d, tD + 32 * cc);
                TCGEN05_WAIT_LD();
                float v[32];
#pragma unroll
                for (int j = 0; j < 32; ++j)
                    v[j] = fmaxf(__uint_as_float(d[j]) + b2v, 0.0f) * w3v;
#pragma unroll
                for (int m = 16; m > 0; m >>= 1) {
#pragma unroll
                    for (int j = 0; j < m; ++j) {
                        float x = (lane & m) ? v[j] : v[j + m];
                        float y = __shfl_xor_sync(0xffffffffu, x, m);
                        v[j] = ((lane & m) ? v[j + m] : v[j]) + y;
                    }
                }
                red[sp * 128 + cc * 32 + lane] = v[0];
            }
            if (elect_one()) MBARRIER_ARRIVE(sb + BAR_DDONE + 8 * b);

            NAMED_BAR(1, 256);             // red[] writes visible
            if (tt2 < TILE_M) {
                int e = t * TILE_M + tt2;
                if (e < E)
                    out[e] = red[tt2] + red[128 + tt2] + red[256 + tt2] +
                             red[384 + tt2] + b3v;
            }
            NAMED_BAR(1, 256);             // red[] consumed before next iter
        }
    }

    __syncthreads();
    if (tid == 0) {
        MBARRIER_INVAL(sb + BAR_FULL);  MBARRIER_INVAL(sb + BAR_FULL + 8);
        MBARRIER_INVAL(sb + BAR_EMPTY); MBARRIER_INVAL(sb + BAR_EMPTY + 8);
        MBARRIER_INVAL(sb + BAR_MMA);   MBARRIER_INVAL(sb + BAR_MMA + 8);
        MBARRIER_INVAL(sb + BAR_DDONE); MBARRIER_INVAL(sb + BAR_DDONE + 8);
    }
    __syncthreads();
    if (wid == 0) TCGEN05_DEALLOC(tmem, 512);
#else
    (void)ei; (void)b1g; (void)b2g; (void)W3g;
    int stride = gridDim.x * blockDim.x;
    for (int e = blockIdx.x * blockDim.x + threadIdx.x; e < E; e += stride)
        out[e] = b3g[0];
#endif
}

// Full-precision standalone fallback (launched only if tc kernels unavailable).
__global__ __launch_bounds__(256, 1)
void edge_mlp_ref_kernel(const float* __restrict__ x1,
                         const float* __restrict__ x2,
                         const int* __restrict__ ei,
                         const float* __restrict__ W1, const float* __restrict__ b1,
                         const float* __restrict__ W2, const float* __restrict__ b2,
                         const float* __restrict__ W3, const float* __restrict__ b3,
                         float* __restrict__ out, int E) {
    int stride = gridDim.x * blockDim.x;
    for (int e = blockIdx.x * blockDim.x + threadIdx.x; e < E; e += stride) {
        const float* xs = x1 + (long long)ei[e] * 128;
        const float* xt = x2 + (long long)ei[E + e] * 128;
        float h1[128], h2[128];
        for (int f = 0; f < 128; ++f) {
            float a = b1[f];
            for (int k = 0; k < 128; ++k) a += xs[k] * W1[k * 128 + f];
            for (int k = 0; k < 128; ++k) a += xt[k] * W1[(128 + k) * 128 + f];
            h1[f] = fmaxf(a, 0.0f);
        }
        for (int g2 = 0; g2 < 128; ++g2) {
            float a = b2[g2];
            for (int f = 0; f < 128; ++f) a += h1[f] * W2[f * 128 + g2];
            h2[g2] = fmaxf(a, 0.0f);
        }
        float acc = b3[0];
        for (int g2 = 0; g2 < 128; ++g2) acc += h2[g2] * W3[g2];
        out[e] = acc;
    }
}

extern "C" void kernel_launch(void* const* d_in, const int* in_sizes, int n_in,
                              void* d_out, int out_size) {
    const float* x1 = (const float*)d_in[0];
    const float* x2 = (const float*)d_in[1];
    const int*   ei = (const int*)d_in[2];
    const float* W1 = (const float*)d_in[3];
    const float* b1 = (const float*)d_in[4];
    const float* W2 = (const float*)d_in[5];
    const float* b2 = (const float*)d_in[6];
    const float* W3 = (const float*)d_in[7];
    const float* b3 = (const float*)d_in[8];
    float*       out = (float*)d_out;

    int E = in_sizes[2] / 2;
    int N = in_sizes[0] / 128;

    static int use_tc = -1;
    if (use_tc < 0) {
        cudaFuncAttributes attr;
        cudaError_t err = cudaFuncGetAttributes(&attr, edge_kernel);
        use_tc = (err == cudaSuccess && attr.maxThreadsPerBlock >= NT) ? 1 : 0;
        if (use_tc) {
            if (cudaFuncSetAttribute(node_kernel,
                                     cudaFuncAttributeMaxDynamicSharedMemorySize,
                                     A_TOTAL) != cudaSuccess) use_tc = 0;
            if (cudaFuncSetAttribute(edge_kernel,
                                     cudaFuncAttributeMaxDynamicSharedMemorySize,
                                     B_TOTAL) != cudaSuccess) use_tc = 0;
        }
        cudaGetLastError();  // clear probe state
    }

    if (use_tc && N <= MAXN) {
        prep_kernel<<<96, 256>>>(W1, W2);
        node_kernel<<<GRID, NT, A_TOTAL>>>(x1, x2, N);
        edge_kernel<<<GRID, NT, B_TOTAL>>>(ei, b1, b2, W3, b3, out, E);
    } else {
        edge_mlp_ref_kernel<<<GRID, 256>>>(x1, x2, ei, W1, b1, W2, b2, W3, b3,
                                           out, E);
    }
}

// round 15
// speedup vs baseline: 1.2380x; 1.2380x over previous
#include <cuda_runtime.h>
#include <cuda_bf16.h>
#include <cstdint>

// ---------------------------------------------------------------------------
// Fused edge-MLP, algebraically restructured (R12 skeleton, high-MLP gather):
//   y1 = x1 @ W1[:128]   (per NODE, 100K rows)   -- node_kernel
//   y2 = x2 @ W1[128:]   (per NODE)
//   per edge: h = relu(y1[src] + y2[dst] + b1)   -- edge_kernel (gather=combine)
//             D2[g,e] = sum_f W2[f,g] * h[e,f]   (tcgen05, W2^T in TMEM)
//             out = relu(D2+b2).W3 + b3
// 3-term bf16 split everywhere = fp32-class accuracy.
// Edge kernel TMEM: W2h 0-63 | W2l 64-127 | D0 128-255 | D1 256-383.
// Double-buffered H (SMEM) + D (TMEM): chain2(t) overlaps epilogue(t-1).
// Gather issues all 16 row-loads per warp up front (MLP 16).
// ---------------------------------------------------------------------------

#if defined(__CUDA_ARCH__) && defined(__CUDA_ARCH_FEAT_SM103_ALL)
#define EDGE_USE_TC 1
#else
#define EDGE_USE_TC 0
#endif

#define NT      512
#define TILE_M  128
#define GRID    148
#define MAXN    100096

// idesc kind::f16: F32 accum, BF16 a/b, N=128, M=128
#define IDESC   0x8200490u

// node kernel SMEM
#define A_PH      0
#define A_PL      32768
#define A_TMEMPTR 65536
#define A_BAR     65544
#define A_TOTAL   65568

// edge kernel SMEM: H buffers (hi|lo) x2, reduction, control
#define B_H(b)    ((b) * 65536)            // HH at +0 (32KB), HL at +32768
#define B_RED     131072
#define B_TMEMPTR 133120
#define B_C2B     133128                   // 2 mbarriers
#define B_TOTAL   133152

// Prepared weights (transposed+packed for TMEM A-operand):
// word(m, c) = bf16(W[2c, m]) | bf16(W[2c+1, m])<<16  (hi and lo splits)
__device__ __align__(16) uint32_t g_W1at_h[8192];   // W1[0:128]^T  [m=128][c=64]
__device__ __align__(16) uint32_t g_W1at_l[8192];
__device__ __align__(16) uint32_t g_W1bt_h[8192];   // W1[128:256]^T
__device__ __align__(16) uint32_t g_W1bt_l[8192];
__device__ __align__(16) uint32_t g_W2t_h[8192];    // W2^T
__device__ __align__(16) uint32_t g_W2t_l[8192];

// Per-node layer-1 partials (fp32), written by node_kernel.
__device__ __align__(16) float g_y1[(size_t)MAXN * 128];
__device__ __align__(16) float g_y2[(size_t)MAXN * 128];

__device__ __forceinline__ int sw128(int off) { return off ^ ((off >> 3) & 0x70); }

#if EDGE_USE_TC

__device__ __forceinline__ uint32_t smem_u32_of(const void* p) {
    uint32_t a;
    asm("{ .reg .u64 t; cvta.to.shared.u64 t, %1; cvt.u32.u64 %0, t; }"
        : "=r"(a) : "l"(p));
    return a;
}
__device__ __forceinline__ uint32_t elect_one() {
    uint32_t pred;
    asm volatile("{ .reg .pred p; elect.sync _|p, 0xFFFFFFFF; selp.b32 %0, 1, 0, p; }"
                 : "=r"(pred));
    return pred;
}
__device__ __forceinline__ uint64_t smem_desc(uint32_t addr) {
    // SW128, Blackwell version=1, SBO=64, LBO=1 (K-major)
    return 0x4000404000010000ULL | ((uint64_t)(addr >> 4) & 0x3FFF);
}
__device__ __forceinline__ void mma_f16_ts(uint32_t d_tmem, uint32_t a_tmem,
                                           uint64_t b_desc, uint32_t en) {
    asm volatile(
        "{\n\t.reg .pred p;\n\tsetp.ne.u32 p, %4, 0;\n\t"
        "tcgen05.mma.cta_group::1.kind::f16 [%0], [%1], %2, %3, {%5,%5,%5,%5}, p;\n\t}"
        :: "r"(d_tmem), "r"(a_tmem), "l"(b_desc), "r"(IDESC), "r"(en), "r"(0u)
        : "memory");
}

#define TCGEN05_ALLOC(sa, n) \
    asm volatile("tcgen05.alloc.cta_group::1.sync.aligned.shared::cta.b32 [%0], %1;" \
                 :: "r"((uint32_t)(sa)), "r"((uint32_t)(n)) : "memory")
#define TCGEN05_DEALLOC(t, n) \
    asm volatile("tcgen05.dealloc.cta_group::1.sync.aligned.b32 %0, %1;" \
                 :: "r"(t), "r"((uint32_t)(n)))
#define TCGEN05_COMMIT(mb) \
    asm volatile("tcgen05.commit.cta_group::1.mbarrier::arrive::one.shared::cluster.b64 [%0];" \
                 :: "r"((uint32_t)(mb)) : "memory")
#define TCGEN05_WAIT_LD()  asm volatile("tcgen05.wait::ld.sync.aligned;" ::: "memory")
#define TCGEN05_WAIT_ST()  asm volatile("tcgen05.wait::st.sync.aligned;" ::: "memory")
#define TCGEN05_FENCE_BEFORE() asm volatile("tcgen05.fence::before_thread_sync;" ::: "memory")
#define TCGEN05_FENCE_AFTER()  asm volatile("tcgen05.fence::after_thread_sync;" ::: "memory")
#define FENCE_ASYNC() asm volatile("fence.proxy.async.shared::cta;" ::: "memory")
#define MBARRIER_INIT(mb, c) \
    asm volatile("mbarrier.init.shared.b64 [%0], %1;" :: "r"((uint32_t)(mb)), "r"((uint32_t)(c)) : "memory")
#define MBARRIER_INVAL(mb) \
    asm volatile("mbarrier.inval.shared.b64 [%0];" :: "r"((uint32_t)(mb)) : "memory")

#define MBARRIER_WAIT_PARITY(mb, ph) do {                                          \
    uint32_t _m = (uint32_t)(mb), _p = (uint32_t)(ph), _done;                      \
    asm volatile("{\n\t.reg .pred p;\n\t"                                          \
        "mbarrier.try_wait.parity.acquire.cta.shared::cta.b64 p, [%1], %2;\n\t"    \
        "selp.b32 %0, 1, 0, p;\n\t}" : "=r"(_done) : "r"(_m), "r"(_p) : "memory"); \
    if (!_done) {                                                                  \
        asm volatile("{\n\t.reg .pred P1;\n\t"                                     \
        "WL_%=:\n\t"                                                               \
        "mbarrier.try_wait.parity.acquire.cta.shared::cta.b64 P1, [%0], %1, 0x989680;\n\t" \
        "@P1 bra.uni WD_%=;\n\t"                                                   \
        "bra.uni WL_%=;\n\t"                                                       \
        "WD_%=:\n\t}" :: "r"(_m), "r"(_p) : "memory");                             \
    }                                                                              \
} while (0)

#define LDTM_X32(r, a)                                                             \
    asm volatile("tcgen05.ld.sync.aligned.32x32b.x32.b32 "                         \
        "{%0,%1,%2,%3,%4,%5,%6,%7,%8,%9,%10,%11,%12,%13,%14,%15,"                  \
        "%16,%17,%18,%19,%20,%21,%22,%23,%24,%25,%26,%27,%28,%29,%30,%31}, [%32];" \
        : "=r"((r)[0]),"=r"((r)[1]),"=r"((r)[2]),"=r"((r)[3]),                     \
          "=r"((r)[4]),"=r"((r)[5]),"=r"((r)[6]),"=r"((r)[7]),                     \
          "=r"((r)[8]),"=r"((r)[9]),"=r"((r)[10]),"=r"((r)[11]),                   \
          "=r"((r)[12]),"=r"((r)[13]),"=r"((r)[14]),"=r"((r)[15]),                 \
          "=r"((r)[16]),"=r"((r)[17]),"=r"((r)[18]),"=r"((r)[19]),                 \
          "=r"((r)[20]),"=r"((r)[21]),"=r"((r)[22]),"=r"((r)[23]),                 \
          "=r"((r)[24]),"=r"((r)[25]),"=r"((r)[26]),"=r"((r)[27]),                 \
          "=r"((r)[28]),"=r"((r)[29]),"=r"((r)[30]),"=r"((r)[31])                  \
        : "r"(a))

#define STTM_X32(a, r)                                                             \
    asm volatile("tcgen05.st.sync.aligned.32x32b.x32.b32 [%0], "                   \
        "{%1,%2,%3,%4,%5,%6,%7,%8,%9,%10,%11,%12,%13,%14,%15,%16,"                 \
        "%17,%18,%19,%20,%21,%22,%23,%24,%25,%26,%27,%28,%29,%30,%31,%32};"        \
        :: "r"(a),                                                                 \
           "r"((r)[0]),"r"((r)[1]),"r"((r)[2]),"r"((r)[3]),                        \
           "r"((r)[4]),"r"((r)[5]),"r"((r)[6]),"r"((r)[7]),                        \
           "r"((r)[8]),"r"((r)[9]),"r"((r)[10]),"r"((r)[11]),                      \
           "r"((r)[12]),"r"((r)[13]),"r"((r)[14]),"r"((r)[15]),                    \
           "r"((r)[16]),"r"((r)[17]),"r"((r)[18]),"r"((r)[19]),                    \
           "r"((r)[20]),"r"((r)[21]),"r"((r)[22]),"r"((r)[23]),                    \
           "r"((r)[24]),"r"((r)[25]),"r"((r)[26]),"r"((r)[27]),                    \
           "r"((r)[28]),"r"((r)[29]),"r"((r)[30]),"r"((r)[31])                     \
        : "memory")

__device__ __forceinline__ uint32_t pack_bf2f(float a, float b) {
    __nv_bfloat162 t = __floats2bfloat162_rn(a, b);   // .x = low half
    return *reinterpret_cast<uint32_t*>(&t);
}

#endif  // EDGE_USE_TC

// ------------------------------ prep kernel -------------------------------
__global__ void prep_kernel(const float* __restrict__ W1,
                            const float* __restrict__ W2) {
    int i = blockIdx.x * blockDim.x + threadIdx.x;
    const float* src = nullptr;
    uint32_t *dh = nullptr, *dl = nullptr;
    int j = i, kofs = 0;
    if (i < 8192)       { src = W1; dh = g_W1at_h; dl = g_W1at_l; kofs = 0;   }
    else if (i < 16384) { src = W1; dh = g_W1bt_h; dl = g_W1bt_l; kofs = 128; j = i - 8192;  }
    else if (i < 24576) { src = W2; dh = g_W2t_h;  dl = g_W2t_l;  kofs = 0;   j = i - 16384; }
    else return;
    int m = j >> 6, c = j & 63;
    float a = src[(kofs + 2 * c) * 128 + m];
    float b = src[(kofs + 2 * c + 1) * 128 + m];
    __nv_bfloat16 ah = __float2bfloat16_rn(a), bh = __float2bfloat16_rn(b);
    float al = a - __bfloat162float(ah), bl = b - __bfloat162float(bh);
    __nv_bfloat162 hi; hi.x = ah; hi.y = bh;
    __nv_bfloat162 lo = __floats2bfloat162_rn(al, bl);
    dh[j] = *reinterpret_cast<uint32_t*>(&hi);
    dl[j] = *reinterpret_cast<uint32_t*>(&lo);
}

// --------------------------- node precompute kernel ------------------------
// y1 = x1 @ W1a, y2 = x2 @ W1b (fp32 out, 3-term bf16 split GEMM).
__global__ __launch_bounds__(NT, 1)
void node_kernel(const float* __restrict__ x1, const float* __restrict__ x2,
                 int N) {
#if EDGE_USE_TC
    extern __shared__ char smem[];
    const uint32_t sb = smem_u32_of(smem);
    const int tid  = threadIdx.x;
    const int lane = tid & 31;
    const int wid  = tid >> 5;
    const int sp   = wid & 3;
    const int cc   = wid >> 2;
    const uint32_t rowbits = (uint32_t)sp << 21;
    const int g    = sp * 32 + lane;

    if (wid == 0) TCGEN05_ALLOC(sb + A_TMEMPTR, 512);
    if (tid == 0) MBARRIER_INIT(sb + A_BAR, 1);
    __syncthreads();
    uint32_t tmem;
    asm volatile("ld.shared.b32 %0, [%1];" : "=r"(tmem) : "r"(sb + A_TMEMPTR));
    const uint32_t tD = tmem + 256;

    // upload W1a (cols 0-127) and W1b (cols 128-255)
    {
        uint32_t ww[32];
        if (wid < 4) {
#pragma unroll
            for (int q = 0; q < 2; ++q) {
#pragma unroll
                for (int i = 0; i < 32; ++i) ww[i] = g_W1at_h[g * 64 + 32 * q + i];
                STTM_X32(tmem + 32 * q + rowbits, ww);
            }
#pragma unroll
            for (int q = 0; q < 2; ++q) {
#pragma unroll
                for (int i = 0; i < 32; ++i) ww[i] = g_W1at_l[g * 64 + 32 * q + i];
                STTM_X32(tmem + 64 + 32 * q + rowbits, ww);
            }
            TCGEN05_WAIT_ST();
        } else if (wid < 8) {
#pragma unroll
            for (int q = 0; q < 2; ++q) {
#pragma unroll
                for (int i = 0; i < 32; ++i) ww[i] = g_W1bt_h[g * 64 + 32 * q + i];
                STTM_X32(tmem + 128 + 32 * q + rowbits, ww);
            }
#pragma unroll
            for (int q = 0; q < 2; ++q) {
#pragma unroll
                for (int i = 0; i < 32; ++i) ww[i] = g_W1bt_l[g * 64 + 32 * q + i];
                STTM_X32(tmem + 192 + 32 * q + rowbits, ww);
            }
            TCGEN05_WAIT_ST();
        }
    }
    TCGEN05_FENCE_BEFORE();
    __syncthreads();

    const int nt1 = (N + 127) / 128;
    const int total = 2 * nt1;
    const int coff = 8 * (lane & 15);
    const int csel = lane >> 4;
    int ph = 0;

    for (int tt = blockIdx.x; tt < total; tt += GRID) {
        const int mt = (tt >= nt1);
        const int tile = mt ? tt - nt1 : tt;
        const float* xb = mt ? x2 : x1;
        float* yb = mt ? g_y2 : g_y1;
        const uint32_t aT = tmem + (mt ? 128u : 0u);

#pragma unroll
        for (int i = 0; i < 8; ++i) {
            int r = wid * 8 + i;
            long long node = (long long)tile * 128 + r;
            float4 v = make_float4(0.f, 0.f, 0.f, 0.f);
            if (node < N)
                v = reinterpret_cast<const float4*>(xb + node * 128)[lane];
            __nv_bfloat162 h0 = __floats2bfloat162_rn(v.x, v.y);
            __nv_bfloat162 h1 = __floats2bfloat162_rn(v.z, v.w);
            uint2 hh = make_uint2(*reinterpret_cast<uint32_t*>(&h0),
                                  *reinterpret_cast<uint32_t*>(&h1));
            uint2 ll = make_uint2(pack_bf2f(v.x - __bfloat162float(h0.x),
                                            v.y - __bfloat162float(h0.y)),
                                  pack_bf2f(v.z - __bfloat162float(h1.x),
                                            v.w - __bfloat162float(h1.y)));
            int off = csel * 16384 + sw128(r * 128 + coff);
            *reinterpret_cast<uint2*>(smem + A_PH + off) = hh;
            *reinterpret_cast<uint2*>(smem + A_PL + off) = ll;
        }
        FENCE_ASYNC();
        __syncthreads();

        if (wid == 4 && elect_one()) {
            TCGEN05_FENCE_AFTER();
#pragma unroll
            for (int pass = 0; pass < 3; ++pass) {
                const uint32_t acol = (pass == 2) ? 64u : 0u;
                const uint32_t bbase = (pass == 1) ? A_PL : A_PH;
                for (int c = 0; c < 2; ++c) {
                    uint64_t bd = smem_desc(sb + bbase + c * 16384);
                    for (int k = 0; k < 4; ++k)
                        mma_f16_ts(tD, aT + acol + (c * 4 + k) * 8, bd + k * 2,
                                   (pass == 0 && c == 0 && k == 0) ? 0u : 1u);
                }
            }
            TCGEN05_COMMIT(sb + A_BAR);
        }
        MBARRIER_WAIT_PARITY(sb + A_BAR, ph); ph ^= 1;
        TCGEN05_FENCE_AFTER();

        uint32_t d[32];
        LDTM_X32(d, tD + 32 * cc);
        TCGEN05_WAIT_LD();
#pragma unroll
        for (int j = 0; j < 32; ++j) {
            long long node = (long long)tile * 128 + cc * 32 + j;
            if (node < N) yb[node * 128 + g] = __uint_as_float(d[j]);
        }
    }

    __syncthreads();
    if (tid == 0) MBARRIER_INVAL(sb + A_BAR);
    __syncthreads();
    if (wid == 0) TCGEN05_DEALLOC(tmem, 512);
#else
    (void)x1; (void)x2; (void)N;
#endif
}

// ------------------------------ edge kernel --------------------------------
__global__ __launch_bounds__(NT, 1)
void edge_kernel(const int* __restrict__ ei,
                 const float* __restrict__ b1g,
                 const float* __restrict__ b2g,
                 const float* __restrict__ W3g,
                 const float* __restrict__ b3g,
                 float* __restrict__ out, int E) {
#if EDGE_USE_TC
    extern __shared__ char smem[];
    const uint32_t sb = smem_u32_of(smem);
    const int tid  = threadIdx.x;
    const int lane = tid & 31;
    const int wid  = tid >> 5;
    const int sp   = wid & 3;
    const int cc   = wid >> 2;
    const uint32_t rowbits = (uint32_t)sp << 21;
    const int g    = sp * 32 + lane;
    const int ntiles = (E + TILE_M - 1) / TILE_M;

    if (wid == 0) TCGEN05_ALLOC(sb + B_TMEMPTR, 512);
    if (tid == 0) { MBARRIER_INIT(sb + B_C2B, 1); MBARRIER_INIT(sb + B_C2B + 8, 1); }
    __syncthreads();
    uint32_t tmem;
    asm volatile("ld.shared.b32 %0, [%1];" : "=r"(tmem) : "r"(sb + B_TMEMPTR));

    // upload W2 (hi cols 0-63, lo cols 64-127)
    if (wid < 4) {
        uint32_t ww[32];
#pragma unroll
        for (int q = 0; q < 2; ++q) {
#pragma unroll
            for (int i = 0; i < 32; ++i) ww[i] = g_W2t_h[g * 64 + 32 * q + i];
            STTM_X32(tmem + 32 * q + rowbits, ww);
        }
#pragma unroll
        for (int q = 0; q < 2; ++q) {
#pragma unroll
            for (int i = 0; i < 32; ++i) ww[i] = g_W2t_l[g * 64 + 32 * q + i];
            STTM_X32(tmem + 64 + 32 * q + rowbits, ww);
        }
        TCGEN05_WAIT_ST();
    }
    TCGEN05_FENCE_BEFORE();
    __syncthreads();

    // per-lane constants
    const float4 b1v4 = reinterpret_cast<const float4*>(b1g)[lane];
    const float b2v = b2g[g];
    const float w3v = W3g[g];
    const float b3v = b3g[0];
    const int coff = 8 * (lane & 15);
    const int csel = lane >> 4;
    const int mbase = wid * 8;

    // gather+combine tile tt into H buffer b; ALL 16 row-loads issued before
    // any conversion (MLP 16) to hide L2 latency.
    auto gather_combine = [&](int tt, int b) {
        int eidx = tt * TILE_M + mbase + (lane & 7);
        int nd = -1;
        if (lane < 16 && eidx < E)
            nd = ei[(lane >= 8 ? E : 0) + eidx];
        float4 va[8], vb[8];
#pragma unroll
        for (int i = 0; i < 8; ++i) {
            int s = __shfl_sync(0xffffffffu, nd, i);
            int d = __shfl_sync(0xffffffffu, nd, 8 + i);
            va[i] = (s >= 0)
                ? reinterpret_cast<const float4*>(g_y1 + (long long)s * 128)[lane]
                : make_float4(0.f, 0.f, 0.f, 0.f);
            vb[i] = (d >= 0)
                ? reinterpret_cast<const float4*>(g_y2 + (long long)d * 128)[lane]
                : make_float4(0.f, 0.f, 0.f, 0.f);
        }
#pragma unroll
        for (int i = 0; i < 8; ++i) {
            int m = mbase + i;
            float v0 = fmaxf(va[i].x + vb[i].x + b1v4.x, 0.f);
            float v1 = fmaxf(va[i].y + vb[i].y + b1v4.y, 0.f);
            float v2 = fmaxf(va[i].z + vb[i].z + b1v4.z, 0.f);
            float v3 = fmaxf(va[i].w + vb[i].w + b1v4.w, 0.f);
            __nv_bfloat162 h0 = __floats2bfloat162_rn(v0, v1);
            __nv_bfloat162 h1 = __floats2bfloat162_rn(v2, v3);
            uint2 hh = make_uint2(*reinterpret_cast<uint32_t*>(&h0),
                                  *reinterpret_cast<uint32_t*>(&h1));
            uint2 ll = make_uint2(pack_bf2f(v0 - __bfloat162float(h0.x),
                                            v1 - __bfloat162float(h0.y)),
                                  pack_bf2f(v2 - __bfloat162float(h1.x),
                                            v3 - __bfloat162float(h1.y)));
            int off = csel * 16384 + sw128(m * 128 + coff);
            *reinterpret_cast<uint2*>(smem + B_H(b) + off) = hh;
            *reinterpret_cast<uint2*>(smem + B_H(b) + 32768 + off) = ll;
        }
        FENCE_ASYNC();
    };

    auto issue_chain2 = [&](int b) {
        TCGEN05_FENCE_AFTER();
        const uint32_t tD = tmem + 128 + 128 * (uint32_t)b;
#pragma unroll
        for (int pass = 0; pass < 3; ++pass) {
            const uint32_t acol = (pass == 2) ? 64u : 0u;
            const uint32_t bbase = B_H(b) + ((pass == 1) ? 32768u : 0u);
            for (int c = 0; c < 2; ++c) {
                uint64_t bd = smem_desc(sb + bbase + c * 16384);
                for (int k = 0; k < 4; ++k)
                    mma_f16_ts(tD, tmem + acol + (c * 4 + k) * 8, bd + k * 2,
                               (pass == 0 && c == 0 && k == 0) ? 0u : 1u);
            }
        }
        TCGEN05_COMMIT(sb + B_C2B + 8 * b);
    };

    auto epilogue = [&](int pt, int pb, int& phref) {
        MBARRIER_WAIT_PARITY(sb + B_C2B + 8 * pb, phref); phref ^= 1;
        TCGEN05_FENCE_AFTER();
        const uint32_t tD = tmem + 128 + 128 * (uint32_t)pb;
        uint32_t d2[32];
        LDTM_X32(d2, tD + 32 * cc);
        TCGEN05_WAIT_LD();
        float v[32];
#pragma unroll
        for (int j = 0; j < 32; ++j)
            v[j] = fmaxf(__uint_as_float(d2[j]) + b2v, 0.0f) * w3v;
#pragma unroll
        for (int m = 16; m > 0; m >>= 1) {
#pragma unroll
            for (int j = 0; j < m; ++j) {
                float x = (lane & m) ? v[j] : v[j + m];
                float y = __shfl_xor_sync(0xffffffffu, x, m);
                v[j] = ((lane & m) ? v[j + m] : v[j]) + y;
            }
        }
        ((float*)(smem + B_RED))[sp * 128 + cc * 32 + lane] = v[0];
        __syncthreads();
        if (tid < TILE_M) {
            int e = pt * TILE_M + tid;
            if (e < E) {
                const float* red = (const float*)(smem + B_RED);
                out[e] = red[tid] + red[128 + tid] + red[256 + tid] +
                         red[384 + tid] + b3v;
            }
        }
    };

    int ph2[2] = {0, 0};
    int iter = 0, pend_t = -1;
    for (int t = blockIdx.x; t < ntiles; t += GRID, ++iter) {
        const int b = iter & 1;
        gather_combine(t, b);
        __syncthreads();                       // H[b] ready; prev drains done
        if (wid == 4 && elect_one()) issue_chain2(b);
        if (pend_t >= 0) epilogue(pend_t, b ^ 1, ph2[b ^ 1]);
        pend_t = t;
    }
    if (pend_t >= 0) {
        const int pb = (iter - 1) & 1;
        epilogue(pend_t, pb, ph2[pb]);
    }

    __syncthreads();
    if (tid == 0) { MBARRIER_INVAL(sb + B_C2B); MBARRIER_INVAL(sb + B_C2B + 8); }
    __syncthreads();
    if (wid == 0) TCGEN05_DEALLOC(tmem, 512);
#else
    (void)ei; (void)b1g; (void)b2g; (void)W3g;
    int stride = gridDim.x * blockDim.x;
    for (int e = blockIdx.x * blockDim.x + threadIdx.x; e < E; e += stride)
        out[e] = b3g[0];
#endif
}

// Full-precision standalone fallback (launched only if tc kernels unavailable).
__global__ __launch_bounds__(256, 1)
void edge_mlp_ref_kernel(const float* __restrict__ x1,
                         const float* __restrict__ x2,
                         const int* __restrict__ ei,
                         const float* __restrict__ W1, const float* __restrict__ b1,
                         const float* __restrict__ W2, const float* __restrict__ b2,
                         const float* __restrict__ W3, const float* __restrict__ b3,
                         float* __restrict__ out, int E) {
    int stride = gridDim.x * blockDim.x;
    for (int e = blockIdx.x * blockDim.x + threadIdx.x; e < E; e += stride) {
        const float* xs = x1 + (long long)ei[e] * 128;
        const float* xt = x2 + (long long)ei[E + e] * 128;
        float h1[128], h2[128];
        for (int f = 0; f < 128; ++f) {
            float a = b1[f];
            for (int k = 0; k < 128; ++k) a += xs[k] * W1[k * 128 + f];
            for (int k = 0; k < 128; ++k) a += xt[k] * W1[(128 + k) * 128 + f];
            h1[f] = fmaxf(a, 0.0f);
        }
        for (int g2 = 0; g2 < 128; ++g2) {
            float a = b2[g2];
            for (int f = 0; f < 128; ++f) a += h1[f] * W2[f * 128 + g2];
            h2[g2] = fmaxf(a, 0.0f);
        }
        float acc = b3[0];
        for (int g2 = 0; g2 < 128; ++g2) acc += h2[g2] * W3[g2];
        out[e] = acc;
    }
}

extern "C" void kernel_launch(void* const* d_in, const int* in_sizes, int n_in,
                              void* d_out, int out_size) {
    const float* x1 = (const float*)d_in[0];
    const float* x2 = (const float*)d_in[1];
    const int*   ei = (const int*)d_in[2];
    const float* W1 = (const float*)d_in[3];
    const float* b1 = (const float*)d_in[4];
    const float* W2 = (const float*)d_in[5];
    const float* b2 = (const float*)d_in[6];
    const float* W3 = (const float*)d_in[7];
    const float* b3 = (const float*)d_in[8];
    float*       out = (float*)d_out;

    int E = in_sizes[2] / 2;
    int N = in_sizes[0] / 128;

    static int use_tc = -1;
    if (use_tc < 0) {
        cudaFuncAttributes attr;
        cudaError_t err = cudaFuncGetAttributes(&attr, edge_kernel);
        use_tc = (err == cudaSuccess && attr.maxThreadsPerBlock >= NT) ? 1 : 0;
        if (use_tc) {
            if (cudaFuncSetAttribute(node_kernel,
                                     cudaFuncAttributeMaxDynamicSharedMemorySize,
                                     A_TOTAL) != cudaSuccess) use_tc = 0;
            if (cudaFuncSetAttribute(edge_kernel,
                                     cudaFuncAttributeMaxDynamicSharedMemorySize,
                                     B_TOTAL) != cudaSuccess) use_tc = 0;
        }
        cudaGetLastError();  // clear probe state
    }

    if (use_tc && N <= MAXN) {
        prep_kernel<<<96, 256>>>(W1, W2);
        node_kernel<<<GRID, NT, A_TOTAL>>>(x1, x2, N);
        edge_kernel<<<GRID, NT, B_TOTAL>>>(ei, b1, b2, W3, b3, out, E);
    } else {
        edge_mlp_ref_kernel<<<GRID, 256>>>(x1, x2, ei, W1, b1, W2, b2, W3, b3,
                                           out, E);
    }
}

// round 16
// speedup vs baseline: 1.3748x; 1.1105x over previous
#include <cuda_runtime.h>
#include <cuda_bf16.h>
#include <cstdint>

// ---------------------------------------------------------------------------
// Fused edge-MLP, algebraically restructured (R12 skeleton + drain/gather
// overlap in the edge loop):
//   y1 = x1 @ W1[:128]   (per NODE)   -- node_kernel
//   y2 = x2 @ W1[128:]   (per NODE)
//   per edge: h = relu(y1[src] + y2[dst] + b1)   -- edge_kernel
//             D2[g,e] = sum_f W2[f,g] * h[e,f]   (tcgen05, W2^T in TMEM)
//             out = relu(D2+b2).W3 + b3
// 3-term bf16 split everywhere = fp32-class accuracy.
// Edge TMEM: W2h 0-63 | W2l 64-127 | D0 128-255 | D1 256-383.
// Edge loop: drain D(prev) FIRST, fold it under the gather's in-flight loads,
// then convert/STS, sync, issue chain2, store out.
// ---------------------------------------------------------------------------

#if defined(__CUDA_ARCH__) && defined(__CUDA_ARCH_FEAT_SM103_ALL)
#define EDGE_USE_TC 1
#else
#define EDGE_USE_TC 0
#endif

#define NT      512
#define TILE_M  128
#define GRID    148
#define MAXN    100096

// idesc kind::f16: F32 accum, BF16 a/b, N=128, M=128
#define IDESC   0x8200490u

// node kernel SMEM
#define A_PH      0
#define A_PL      32768
#define A_TMEMPTR 65536
#define A_BAR     65544
#define A_TOTAL   65568

// edge kernel SMEM: H buffers (hi|lo) x2, reduction, control
#define B_H(b)    ((b) * 65536)            // HH at +0 (32KB), HL at +32768
#define B_RED     131072
#define B_TMEMPTR 133120
#define B_C2B     133128                   // 2 mbarriers
#define B_TOTAL   133152

// Prepared weights (transposed+packed for TMEM A-operand):
// word(m, c) = bf16(W[2c, m]) | bf16(W[2c+1, m])<<16  (hi and lo splits)
__device__ __align__(16) uint32_t g_W1at_h[8192];   // W1[0:128]^T  [m=128][c=64]
__device__ __align__(16) uint32_t g_W1at_l[8192];
__device__ __align__(16) uint32_t g_W1bt_h[8192];   // W1[128:256]^T
__device__ __align__(16) uint32_t g_W1bt_l[8192];
__device__ __align__(16) uint32_t g_W2t_h[8192];    // W2^T
__device__ __align__(16) uint32_t g_W2t_l[8192];

// Per-node layer-1 partials (fp32), written by node_kernel.
__device__ __align__(16) float g_y1[(size_t)MAXN * 128];
__device__ __align__(16) float g_y2[(size_t)MAXN * 128];

__device__ __forceinline__ int sw128(int off) { return off ^ ((off >> 3) & 0x70); }

#if EDGE_USE_TC

__device__ __forceinline__ uint32_t smem_u32_of(const void* p) {
    uint32_t a;
    asm("{ .reg .u64 t; cvta.to.shared.u64 t, %1; cvt.u32.u64 %0, t; }"
        : "=r"(a) : "l"(p));
    return a;
}
__device__ __forceinline__ uint32_t elect_one() {
    uint32_t pred;
    asm volatile("{ .reg .pred p; elect.sync _|p, 0xFFFFFFFF; selp.b32 %0, 1, 0, p; }"
                 : "=r"(pred));
    return pred;
}
__device__ __forceinline__ uint64_t smem_desc(uint32_t addr) {
    // SW128, Blackwell version=1, SBO=64, LBO=1 (K-major)
    return 0x4000404000010000ULL | ((uint64_t)(addr >> 4) & 0x3FFF);
}
__device__ __forceinline__ void mma_f16_ts(uint32_t d_tmem, uint32_t a_tmem,
                                           uint64_t b_desc, uint32_t en) {
    asm volatile(
        "{\n\t.reg .pred p;\n\tsetp.ne.u32 p, %4, 0;\n\t"
        "tcgen05.mma.cta_group::1.kind::f16 [%0], [%1], %2, %3, {%5,%5,%5,%5}, p;\n\t}"
        :: "r"(d_tmem), "r"(a_tmem), "l"(b_desc), "r"(IDESC), "r"(en), "r"(0u)
        : "memory");
}

#define TCGEN05_ALLOC(sa, n) \
    asm volatile("tcgen05.alloc.cta_group::1.sync.aligned.shared::cta.b32 [%0], %1;" \
                 :: "r"((uint32_t)(sa)), "r"((uint32_t)(n)) : "memory")
#define TCGEN05_DEALLOC(t, n) \
    asm volatile("tcgen05.dealloc.cta_group::1.sync.aligned.b32 %0, %1;" \
                 :: "r"(t), "r"((uint32_t)(n)))
#define TCGEN05_COMMIT(mb) \
    asm volatile("tcgen05.commit.cta_group::1.mbarrier::arrive::one.shared::cluster.b64 [%0];" \
                 :: "r"((uint32_t)(mb)) : "memory")
#define TCGEN05_WAIT_LD()  asm volatile("tcgen05.wait::ld.sync.aligned;" ::: "memory")
#define TCGEN05_WAIT_ST()  asm volatile("tcgen05.wait::st.sync.aligned;" ::: "memory")
#define TCGEN05_FENCE_BEFORE() asm volatile("tcgen05.fence::before_thread_sync;" ::: "memory")
#define TCGEN05_FENCE_AFTER()  asm volatile("tcgen05.fence::after_thread_sync;" ::: "memory")
#define FENCE_ASYNC() asm volatile("fence.proxy.async.shared::cta;" ::: "memory")
#define MBARRIER_INIT(mb, c) \
    asm volatile("mbarrier.init.shared.b64 [%0], %1;" :: "r"((uint32_t)(mb)), "r"((uint32_t)(c)) : "memory")
#define MBARRIER_INVAL(mb) \
    asm volatile("mbarrier.inval.shared.b64 [%0];" :: "r"((uint32_t)(mb)) : "memory")

#define MBARRIER_WAIT_PARITY(mb, ph) do {                                          \
    uint32_t _m = (uint32_t)(mb), _p = (uint32_t)(ph), _done;                      \
    asm volatile("{\n\t.reg .pred p;\n\t"                                          \
        "mbarrier.try_wait.parity.acquire.cta.shared::cta.b64 p, [%1], %2;\n\t"    \
        "selp.b32 %0, 1, 0, p;\n\t}" : "=r"(_done) : "r"(_m), "r"(_p) : "memory"); \
    if (!_done) {                                                                  \
        asm volatile("{\n\t.reg .pred P1;\n\t"                                     \
        "WL_%=:\n\t"                                                               \
        "mbarrier.try_wait.parity.acquire.cta.shared::cta.b64 P1, [%0], %1, 0x989680;\n\t" \
        "@P1 bra.uni WD_%=;\n\t"                                                   \
        "bra.uni WL_%=;\n\t"                                                       \
        "WD_%=:\n\t}" :: "r"(_m), "r"(_p) : "memory");                             \
    }                                                                              \
} while (0)

#define LDTM_X32(r, a)                                                             \
    asm volatile("tcgen05.ld.sync.aligned.32x32b.x32.b32 "                         \
        "{%0,%1,%2,%3,%4,%5,%6,%7,%8,%9,%10,%11,%12,%13,%14,%15,"                  \
        "%16,%17,%18,%19,%20,%21,%22,%23,%24,%25,%26,%27,%28,%29,%30,%31}, [%32];" \
        : "=r"((r)[0]),"=r"((r)[1]),"=r"((r)[2]),"=r"((r)[3]),                     \
          "=r"((r)[4]),"=r"((r)[5]),"=r"((r)[6]),"=r"((r)[7]),                     \
          "=r"((r)[8]),"=r"((r)[9]),"=r"((r)[10]),"=r"((r)[11]),                   \
          "=r"((r)[12]),"=r"((r)[13]),"=r"((r)[14]),"=r"((r)[15]),                 \
          "=r"((r)[16]),"=r"((r)[17]),"=r"((r)[18]),"=r"((r)[19]),                 \
          "=r"((r)[20]),"=r"((r)[21]),"=r"((r)[22]),"=r"((r)[23]),                 \
          "=r"((r)[24]),"=r"((r)[25]),"=r"((r)[26]),"=r"((r)[27]),                 \
          "=r"((r)[28]),"=r"((r)[29]),"=r"((r)[30]),"=r"((r)[31])                  \
        : "r"(a))

#define STTM_X32(a, r)                                                             \
    asm volatile("tcgen05.st.sync.aligned.32x32b.x32.b32 [%0], "                   \
        "{%1,%2,%3,%4,%5,%6,%7,%8,%9,%10,%11,%12,%13,%14,%15,%16,"                 \
        "%17,%18,%19,%20,%21,%22,%23,%24,%25,%26,%27,%28,%29,%30,%31,%32};"        \
        :: "r"(a),                                                                 \
           "r"((r)[0]),"r"((r)[1]),"r"((r)[2]),"r"((r)[3]),                        \
           "r"((r)[4]),"r"((r)[5]),"r"((r)[6]),"r"((r)[7]),                        \
           "r"((r)[8]),"r"((r)[9]),"r"((r)[10]),"r"((r)[11]),                      \
           "r"((r)[12]),"r"((r)[13]),"r"((r)[14]),"r"((r)[15]),                    \
           "r"((r)[16]),"r"((r)[17]),"r"((r)[18]),"r"((r)[19]),                    \
           "r"((r)[20]),"r"((r)[21]),"r"((r)[22]),"r"((r)[23]),                    \
           "r"((r)[24]),"r"((r)[25]),"r"((r)[26]),"r"((r)[27]),                    \
           "r"((r)[28]),"r"((r)[29]),"r"((r)[30]),"r"((r)[31])                     \
        : "memory")

__device__ __forceinline__ uint32_t pack_bf2f(float a, float b) {
    __nv_bfloat162 t = __floats2bfloat162_rn(a, b);   // .x = low half
    return *reinterpret_cast<uint32_t*>(&t);
}

#endif  // EDGE_USE_TC

// ------------------------------ prep kernel -------------------------------
__global__ void prep_kernel(const float* __restrict__ W1,
                            const float* __restrict__ W2) {
    int i = blockIdx.x * blockDim.x + threadIdx.x;
    const float* src = nullptr;
    uint32_t *dh = nullptr, *dl = nullptr;
    int j = i, kofs = 0;
    if (i < 8192)       { src = W1; dh = g_W1at_h; dl = g_W1at_l; kofs = 0;   }
    else if (i < 16384) { src = W1; dh = g_W1bt_h; dl = g_W1bt_l; kofs = 128; j = i - 8192;  }
    else if (i < 24576) { src = W2; dh = g_W2t_h;  dl = g_W2t_l;  kofs = 0;   j = i - 16384; }
    else return;
    int m = j >> 6, c = j & 63;
    float a = src[(kofs + 2 * c) * 128 + m];
    float b = src[(kofs + 2 * c + 1) * 128 + m];
    __nv_bfloat16 ah = __float2bfloat16_rn(a), bh = __float2bfloat16_rn(b);
    float al = a - __bfloat162float(ah), bl = b - __bfloat162float(bh);
    __nv_bfloat162 hi; hi.x = ah; hi.y = bh;
    __nv_bfloat162 lo = __floats2bfloat162_rn(al, bl);
    dh[j] = *reinterpret_cast<uint32_t*>(&hi);
    dl[j] = *reinterpret_cast<uint32_t*>(&lo);
}

// --------------------------- node precompute kernel ------------------------
// y1 = x1 @ W1a, y2 = x2 @ W1b (fp32 out, 3-term bf16 split GEMM).
__global__ __launch_bounds__(NT, 1)
void node_kernel(const float* __restrict__ x1, const float* __restrict__ x2,
                 int N) {
#if EDGE_USE_TC
    extern __shared__ char smem[];
    const uint32_t sb = smem_u32_of(smem);
    const int tid  = threadIdx.x;
    const int lane = tid & 31;
    const int wid  = tid >> 5;
    const int sp   = wid & 3;
    const int cc   = wid >> 2;
    const uint32_t rowbits = (uint32_t)sp << 21;
    const int g    = sp * 32 + lane;

    if (wid == 0) TCGEN05_ALLOC(sb + A_TMEMPTR, 512);
    if (tid == 0) MBARRIER_INIT(sb + A_BAR, 1);
    __syncthreads();
    uint32_t tmem;
    asm volatile("ld.shared.b32 %0, [%1];" : "=r"(tmem) : "r"(sb + A_TMEMPTR));
    const uint32_t tD = tmem + 256;

    // upload W1a (cols 0-127) and W1b (cols 128-255)
    {
        uint32_t ww[32];
        if (wid < 4) {
#pragma unroll
            for (int q = 0; q < 2; ++q) {
#pragma unroll
                for (int i = 0; i < 32; ++i) ww[i] = g_W1at_h[g * 64 + 32 * q + i];
                STTM_X32(tmem + 32 * q + rowbits, ww);
            }
#pragma unroll
            for (int q = 0; q < 2; ++q) {
#pragma unroll
                for (int i = 0; i < 32; ++i) ww[i] = g_W1at_l[g * 64 + 32 * q + i];
                STTM_X32(tmem + 64 + 32 * q + rowbits, ww);
            }
            TCGEN05_WAIT_ST();
        } else if (wid < 8) {
#pragma unroll
            for (int q = 0; q < 2; ++q) {
#pragma unroll
                for (int i = 0; i < 32; ++i) ww[i] = g_W1bt_h[g * 64 + 32 * q + i];
                STTM_X32(tmem + 128 + 32 * q + rowbits, ww);
            }
#pragma unroll
            for (int q = 0; q < 2; ++q) {
#pragma unroll
                for (int i = 0; i < 32; ++i) ww[i] = g_W1bt_l[g * 64 + 32 * q + i];
                STTM_X32(tmem + 192 + 32 * q + rowbits, ww);
            }
            TCGEN05_WAIT_ST();
        }
    }
    TCGEN05_FENCE_BEFORE();
    __syncthreads();

    const int nt1 = (N + 127) / 128;
    const int total = 2 * nt1;
    const int coff = 8 * (lane & 15);
    const int csel = lane >> 4;
    int ph = 0;

    for (int tt = blockIdx.x; tt < total; tt += GRID) {
        const int mt = (tt >= nt1);
        const int tile = mt ? tt - nt1 : tt;
        const float* xb = mt ? x2 : x1;
        float* yb = mt ? g_y2 : g_y1;
        const uint32_t aT = tmem + (mt ? 128u : 0u);

#pragma unroll
        for (int i = 0; i < 8; ++i) {
            int r = wid * 8 + i;
            long long node = (long long)tile * 128 + r;
            float4 v = make_float4(0.f, 0.f, 0.f, 0.f);
            if (node < N)
                v = reinterpret_cast<const float4*>(xb + node * 128)[lane];
            __nv_bfloat162 h0 = __floats2bfloat162_rn(v.x, v.y);
            __nv_bfloat162 h1 = __floats2bfloat162_rn(v.z, v.w);
            uint2 hh = make_uint2(*reinterpret_cast<uint32_t*>(&h0),
                                  *reinterpret_cast<uint32_t*>(&h1));
            uint2 ll = make_uint2(pack_bf2f(v.x - __bfloat162float(h0.x),
                                            v.y - __bfloat162float(h0.y)),
                                  pack_bf2f(v.z - __bfloat162float(h1.x),
                                            v.w - __bfloat162float(h1.y)));
            int off = csel * 16384 + sw128(r * 128 + coff);
            *reinterpret_cast<uint2*>(smem + A_PH + off) = hh;
            *reinterpret_cast<uint2*>(smem + A_PL + off) = ll;
        }
        FENCE_ASYNC();
        __syncthreads();

        if (wid == 4 && elect_one()) {
            TCGEN05_FENCE_AFTER();
#pragma unroll
            for (int pass = 0; pass < 3; ++pass) {
                const uint32_t acol = (pass == 2) ? 64u : 0u;
                const uint32_t bbase = (pass == 1) ? A_PL : A_PH;
                for (int c = 0; c < 2; ++c) {
                    uint64_t bd = smem_desc(sb + bbase + c * 16384);
                    for (int k = 0; k < 4; ++k)
                        mma_f16_ts(tD, aT + acol + (c * 4 + k) * 8, bd + k * 2,
                                   (pass == 0 && c == 0 && k == 0) ? 0u : 1u);
                }
            }
            TCGEN05_COMMIT(sb + A_BAR);
        }
        MBARRIER_WAIT_PARITY(sb + A_BAR, ph); ph ^= 1;
        TCGEN05_FENCE_AFTER();

        uint32_t d[32];
        LDTM_X32(d, tD + 32 * cc);
        TCGEN05_WAIT_LD();
#pragma unroll
        for (int j = 0; j < 32; ++j) {
            long long node = (long long)tile * 128 + cc * 32 + j;
            if (node < N) yb[node * 128 + g] = __uint_as_float(d[j]);
        }
    }

    __syncthreads();
    if (tid == 0) MBARRIER_INVAL(sb + A_BAR);
    __syncthreads();
    if (wid == 0) TCGEN05_DEALLOC(tmem, 512);
#else
    (void)x1; (void)x2; (void)N;
#endif
}

// ------------------------------ edge kernel --------------------------------
__global__ __launch_bounds__(NT, 1)
void edge_kernel(const int* __restrict__ ei,
                 const float* __restrict__ b1g,
                 const float* __restrict__ b2g,
                 const float* __restrict__ W3g,
                 const float* __restrict__ b3g,
                 float* __restrict__ out, int E) {
#if EDGE_USE_TC
    extern __shared__ char smem[];
    const uint32_t sb = smem_u32_of(smem);
    const int tid  = threadIdx.x;
    const int lane = tid & 31;
    const int wid  = tid >> 5;
    const int sp   = wid & 3;
    const int cc   = wid >> 2;
    const uint32_t rowbits = (uint32_t)sp << 21;
    const int g    = sp * 32 + lane;
    const int ntiles = (E + TILE_M - 1) / TILE_M;

    if (wid == 0) TCGEN05_ALLOC(sb + B_TMEMPTR, 512);
    if (tid == 0) { MBARRIER_INIT(sb + B_C2B, 1); MBARRIER_INIT(sb + B_C2B + 8, 1); }
    __syncthreads();
    uint32_t tmem;
    asm volatile("ld.shared.b32 %0, [%1];" : "=r"(tmem) : "r"(sb + B_TMEMPTR));

    // upload W2 (hi cols 0-63, lo cols 64-127)
    if (wid < 4) {
        uint32_t ww[32];
#pragma unroll
        for (int q = 0; q < 2; ++q) {
#pragma unroll
            for (int i = 0; i < 32; ++i) ww[i] = g_W2t_h[g * 64 + 32 * q + i];
            STTM_X32(tmem + 32 * q + rowbits, ww);
        }
#pragma unroll
        for (int q = 0; q < 2; ++q) {
#pragma unroll
            for (int i = 0; i < 32; ++i) ww[i] = g_W2t_l[g * 64 + 32 * q + i];
            STTM_X32(tmem + 64 + 32 * q + rowbits, ww);
        }
        TCGEN05_WAIT_ST();
    }
    TCGEN05_FENCE_BEFORE();
    __syncthreads();

    // per-lane constants
    const float4 b1v4 = reinterpret_cast<const float4*>(b1g)[lane];
    const float b2v = b2g[g];
    const float w3v = W3g[g];
    const float b3v = b3g[0];
    const int coff = 8 * (lane & 15);
    const int csel = lane >> 4;
    const int mbase = wid * 8;
    float* red = (float*)(smem + B_RED);

    auto issue_chain2 = [&](int b) {
        TCGEN05_FENCE_AFTER();
        const uint32_t tD = tmem + 128 + 128 * (uint32_t)b;
#pragma unroll
        for (int pass = 0; pass < 3; ++pass) {
            const uint32_t acol = (pass == 2) ? 64u : 0u;
            const uint32_t bbase = B_H(b) + ((pass == 1) ? 32768u : 0u);
            for (int c = 0; c < 2; ++c) {
                uint64_t bd = smem_desc(sb + bbase + c * 16384);
                for (int k = 0; k < 4; ++k)
                    mma_f16_ts(tD, tmem + acol + (c * 4 + k) * 8, bd + k * 2,
                               (pass == 0 && c == 0 && k == 0) ? 0u : 1u);
            }
        }
        TCGEN05_COMMIT(sb + B_C2B + 8 * b);
    };

    // convert+STS one edge row
    auto put_row = [&](int b, int m, const float4& a4, const float4& c4) {
        float v0 = fmaxf(a4.x + c4.x + b1v4.x, 0.f);
        float v1 = fmaxf(a4.y + c4.y + b1v4.y, 0.f);
        float v2 = fmaxf(a4.z + c4.z + b1v4.z, 0.f);
        float v3 = fmaxf(a4.w + c4.w + b1v4.w, 0.f);
        __nv_bfloat162 h0 = __floats2bfloat162_rn(v0, v1);
        __nv_bfloat162 h1 = __floats2bfloat162_rn(v2, v3);
        uint2 hh = make_uint2(*reinterpret_cast<uint32_t*>(&h0),
                              *reinterpret_cast<uint32_t*>(&h1));
        uint2 ll = make_uint2(pack_bf2f(v0 - __bfloat162float(h0.x),
                                        v1 - __bfloat162float(h0.y)),
                              pack_bf2f(v2 - __bfloat162float(h1.x),
                                        v3 - __bfloat162float(h1.y)));
        int off = csel * 16384 + sw128(m * 128 + coff);
        *reinterpret_cast<uint2*>(smem + B_H(b) + off) = hh;
        *reinterpret_cast<uint2*>(smem + B_H(b) + 32768 + off) = ll;
    };

    int ph2[2] = {0, 0};
    int iter = 0, pend_t = -1;
    for (int t = blockIdx.x; t < ntiles; t += GRID, ++iter) {
        const int b  = iter & 1;
        const int pb = b ^ 1;
        const bool hp = (pend_t >= 0);

        // ---- early drain of previous tile's D (wait already satisfied) ----
        uint32_t d2[32];
        if (hp) {
            MBARRIER_WAIT_PARITY(sb + B_C2B + 8 * pb, ph2[pb]); ph2[pb] ^= 1;
            TCGEN05_FENCE_AFTER();
            LDTM_X32(d2, tmem + 128 + 128 * (uint32_t)pb + 32 * cc);
            TCGEN05_WAIT_LD();
        }

        // ---- edge indices for this tile ----
        int eidx = t * TILE_M + mbase + (lane & 7);
        int nd = -1;
        if (lane < 16 && eidx < E)
            nd = ei[(lane >= 8 ? E : 0) + eidx];

        // ---- phase A: issue 8 loads (edges 0..3) ----
        float4 va[4], vb[4];
#pragma unroll
        for (int i = 0; i < 4; ++i) {
            int s = __shfl_sync(0xffffffffu, nd, i);
            int d = __shfl_sync(0xffffffffu, nd, 8 + i);
            va[i] = (s >= 0)
                ? reinterpret_cast<const float4*>(g_y1 + (long long)s * 128)[lane]
                : make_float4(0.f, 0.f, 0.f, 0.f);
            vb[i] = (d >= 0)
                ? reinterpret_cast<const float4*>(g_y2 + (long long)d * 128)[lane]
                : make_float4(0.f, 0.f, 0.f, 0.f);
        }

        // ---- fold previous D while phase-A loads are in flight ----
        if (hp) {
            float v[32];
#pragma unroll
            for (int j = 0; j < 32; ++j)
                v[j] = fmaxf(__uint_as_float(d2[j]) + b2v, 0.0f) * w3v;
#pragma unroll
            for (int m = 16; m > 0; m >>= 1) {
#pragma unroll
                for (int j = 0; j < m; ++j) {
                    float x = (lane & m) ? v[j] : v[j + m];
                    float y = __shfl_xor_sync(0xffffffffu, x, m);
                    v[j] = ((lane & m) ? v[j + m] : v[j]) + y;
                }
            }
            red[sp * 128 + cc * 32 + lane] = v[0];
        }

        // ---- convert+STS phase A ----
#pragma unroll
        for (int i = 0; i < 4; ++i) put_row(b, mbase + i, va[i], vb[i]);

        // ---- phase B: edges 4..7 ----
#pragma unroll
        for (int i = 0; i < 4; ++i) {
            int s = __shfl_sync(0xffffffffu, nd, 4 + i);
            int d = __shfl_sync(0xffffffffu, nd, 12 + i);
            va[i] = (s >= 0)
                ? reinterpret_cast<const float4*>(g_y1 + (long long)s * 128)[lane]
                : make_float4(0.f, 0.f, 0.f, 0.f);
            vb[i] = (d >= 0)
                ? reinterpret_cast<const float4*>(g_y2 + (long long)d * 128)[lane]
                : make_float4(0.f, 0.f, 0.f, 0.f);
        }
#pragma unroll
        for (int i = 0; i < 4; ++i) put_row(b, mbase + 4 + i, va[i], vb[i]);

        FENCE_ASYNC();
        __syncthreads();                       // A: H(b) + red[] visible
        if (wid == 4 && elect_one()) issue_chain2(b);
        if (hp && tid < TILE_M) {
            int e = pend_t * TILE_M + tid;
            if (e < E)
                out[e] = red[tid] + red[128 + tid] + red[256 + tid] +
                         red[384 + tid] + b3v;
        }
        __syncthreads();                       // B: red consumed
        pend_t = t;
    }

    // ---- drain the final tile ----
    if (pend_t >= 0) {
        const int pb = (iter - 1) & 1;
        MBARRIER_WAIT_PARITY(sb + B_C2B + 8 * pb, ph2[pb]);
        TCGEN05_FENCE_AFTER();
        uint32_t d2[32];
        LDTM_X32(d2, tmem + 128 + 128 * (uint32_t)pb + 32 * cc);
        TCGEN05_WAIT_LD();
        float v[32];
#pragma unroll
        for (int j = 0; j < 32; ++j)
            v[j] = fmaxf(__uint_as_float(d2[j]) + b2v, 0.0f) * w3v;
#pragma unroll
        for (int m = 16; m > 0; m >>= 1) {
#pragma unroll
            for (int j = 0; j < m; ++j) {
                float x = (lane & m) ? v[j] : v[j + m];
                float y = __shfl_xor_sync(0xffffffffu, x, m);
                v[j] = ((lane & m) ? v[j + m] : v[j]) + y;
            }
        }
        red[sp * 128 + cc * 32 + lane] = v[0];
        __syncthreads();
        if (tid < TILE_M) {
            int e = pend_t * TILE_M + tid;
            if (e < E)
                out[e] = red[tid] + red[128 + tid] + red[256 + tid] +
                         red[384 + tid] + b3v;
        }
    }

    __syncthreads();
    if (tid == 0) { MBARRIER_INVAL(sb + B_C2B); MBARRIER_INVAL(sb + B_C2B + 8); }
    __syncthreads();
    if (wid == 0) TCGEN05_DEALLOC(tmem, 512);
#else
    (void)ei; (void)b1g; (void)b2g; (void)W3g;
    int stride = gridDim.x * blockDim.x;
    for (int e = blockIdx.x * blockDim.x + threadIdx.x; e < E; e += stride)
        out[e] = b3g[0];
#endif
}

// Full-precision standalone fallback (launched only if tc kernels unavailable).
__global__ __launch_bounds__(256, 1)
void edge_mlp_ref_kernel(const float* __restrict__ x1,
                         const float* __restrict__ x2,
                         const int* __restrict__ ei,
                         const float* __restrict__ W1, const float* __restrict__ b1,
                         const float* __restrict__ W2, const float* __restrict__ b2,
                         const float* __restrict__ W3, const float* __restrict__ b3,
                         float* __restrict__ out, int E) {
    int stride = gridDim.x * blockDim.x;
    for (int e = blockIdx.x * blockDim.x + threadIdx.x; e < E; e += stride) {
        const float* xs = x1 + (long long)ei[e] * 128;
        const float* xt = x2 + (long long)ei[E + e] * 128;
        float h1[128], h2[128];
        for (int f = 0; f < 128; ++f) {
            float a = b1[f];
            for (int k = 0; k < 128; ++k) a += xs[k] * W1[k * 128 + f];
            for (int k = 0; k < 128; ++k) a += xt[k] * W1[(128 + k) * 128 + f];
            h1[f] = fmaxf(a, 0.0f);
        }
        for (int g2 = 0; g2 < 128; ++g2) {
            float a = b2[g2];
            for (int f = 0; f < 128; ++f) a += h1[f] * W2[f * 128 + g2];
            h2[g2] = fmaxf(a, 0.0f);
        }
        float acc = b3[0];
        for (int g2 = 0; g2 < 128; ++g2) acc += h2[g2] * W3[g2];
        out[e] = acc;
    }
}

extern "C" void kernel_launch(void* const* d_in, const int* in_sizes, int n_in,
                              void* d_out, int out_size) {
    const float* x1 = (const float*)d_in[0];
    const float* x2 = (const float*)d_in[1];
    const int*   ei = (const int*)d_in[2];
    const float* W1 = (const float*)d_in[3];
    const float* b1 = (const float*)d_in[4];
    const float* W2 = (const float*)d_in[5];
    const float* b2 = (const float*)d_in[6];
    const float* W3 = (const float*)d_in[7];
    const float* b3 = (const float*)d_in[8];
    float*       out = (float*)d_out;

    int E = in_sizes[2] / 2;
    int N = in_sizes[0] / 128;

    static int use_tc = -1;
    if (use_tc < 0) {
        cudaFuncAttributes attr;
        cudaError_t err = cudaFuncGetAttributes(&attr, edge_kernel);
        use_tc = (err == cudaSuccess && attr.maxThreadsPerBlock >= NT) ? 1 : 0;
        if (use_tc) {
            if (cudaFuncSetAttribute(node_kernel,
                                     cudaFuncAttributeMaxDynamicSharedMemorySize,
                                     A_TOTAL) != cudaSuccess) use_tc = 0;
            if (cudaFuncSetAttribute(edge_kernel,
                                     cudaFuncAttributeMaxDynamicSharedMemorySize,
                                     B_TOTAL) != cudaSuccess) use_tc = 0;
        }
        cudaGetLastError();  // clear probe state
    }

    if (use_tc && N <= MAXN) {
        prep_kernel<<<96, 256>>>(W1, W2);
        node_kernel<<<GRID, NT, A_TOTAL>>>(x1, x2, N);
        edge_kernel<<<GRID, NT, B_TOTAL>>>(ei, b1, b2, W3, b3, out, E);
    } else {
        edge_mlp_ref_kernel<<<GRID, 256>>>(x1, x2, ei, W1, b1, W2, b2, W3, b3,
                                           out, E);
    }
}